// round 3
// baseline (speedup 1.0000x reference)
#include <cuda_runtime.h>
#include <stdint.h>

// Sampling_26972394619348
// w = z_mean[:,None,:] + exp(0.5*z_log_var)[:,None,:] * epsilon   [B,100,3]
// labels_ext = repeat(labels, 100), emitted as float32 values in d_out
//
// Inputs (metadata order):
//   d_in[0] z_mean    float32 [B,3]
//   d_in[1] z_log_var float32 [B,3]
//   d_in[2] labels    int32 [B]   (JAX x64 disabled -> int32)
//   d_in[3] epsilon   float32 [B,100,3]
// Output buffer: w.flatten() [B*300 fp32] followed by labels_ext [B*100 fp32].
//
// Each thread processes 4 consecutive MC samples = 12 floats = 3 float4.
// 4 | 100 so the 4 samples never cross a batch row; 3 | 12 so the xyz
// component phase inside the 3 float4s is fixed:
//   f4[0] = (x y z x), f4[1] = (y z x y), f4[2] = (z x y z)

// lab_mode: 0 = label slot is 1 fp32 element (int32 input, float output)
//           1 = label slot is 2 fp32 elements (int64 input, raw copy)
//           2 = no label region (defensive)
__global__ void __launch_bounds__(256)
sampling_kernel(const float* __restrict__ zm,
                const float* __restrict__ lv,
                const void* __restrict__ labels,
                const float4* __restrict__ eps4,
                float4* __restrict__ w4,
                char* __restrict__ lab_out,
                int lab_mode,
                long long n_threads)   // = B*25  (B*100 samples / 4)
{
    long long t = (long long)blockIdx.x * blockDim.x + threadIdx.x;
    if (t >= n_threads) return;

    // 25 threads per batch row (100 samples / 4)
    int b = (int)(t / 25);

    float zx = __ldg(&zm[3*b + 0]);
    float zy = __ldg(&zm[3*b + 1]);
    float zz = __ldg(&zm[3*b + 2]);
    float sx = __expf(0.5f * __ldg(&lv[3*b + 0]));
    float sy = __expf(0.5f * __ldg(&lv[3*b + 1]));
    float sz = __expf(0.5f * __ldg(&lv[3*b + 2]));

    long long base = t * 3;          // float4 index into eps / w
    float4 e0 = eps4[base + 0];
    float4 e1 = eps4[base + 1];
    float4 e2 = eps4[base + 2];

    float4 o0, o1, o2;
    o0.x = fmaf(sx, e0.x, zx);
    o0.y = fmaf(sy, e0.y, zy);
    o0.z = fmaf(sz, e0.z, zz);
    o0.w = fmaf(sx, e0.w, zx);

    o1.x = fmaf(sy, e1.x, zy);
    o1.y = fmaf(sz, e1.y, zz);
    o1.z = fmaf(sx, e1.z, zx);
    o1.w = fmaf(sy, e1.w, zy);

    o2.x = fmaf(sz, e2.x, zz);
    o2.y = fmaf(sx, e2.y, zx);
    o2.z = fmaf(sy, e2.z, zy);
    o2.w = fmaf(sz, e2.w, zz);

    w4[base + 0] = o0;
    w4[base + 1] = o1;
    w4[base + 2] = o2;

    if (lab_mode == 0) {
        // int32 label in, float32 numeric value out (4 samples = 1 float4)
        float lf = (float)__ldg((const int*)labels + b);
        reinterpret_cast<float4*>(lab_out)[t] = make_float4(lf, lf, lf, lf);
    } else if (lab_mode == 1) {
        // int64 label in, raw int64 copy out (4 samples = 2x longlong2)
        long long lab = __ldg((const long long*)labels + b);
        longlong2 l2; l2.x = lab; l2.y = lab;
        longlong2* p = reinterpret_cast<longlong2*>(lab_out) + t * 2;
        p[0] = l2;
        p[1] = l2;
    }
}

extern "C" void kernel_launch(void* const* d_in, const int* in_sizes, int n_in,
                              void* d_out, int out_size)
{
    const float* zm     = (const float*)d_in[0];
    const float* lv     = (const float*)d_in[1];
    const void*  labels = d_in[2];
    const float4* eps4  = (const float4*)d_in[3];

    const long long B   = in_sizes[2];            // labels element count
    const long long n_w = B * 300;                // B*100*3 floats of w
    const long long rem = (long long)out_size - n_w;

    int lab_mode;
    if (rem == B * 100)      lab_mode = 0;        // 1 fp32 slot per sample
    else if (rem == B * 200) lab_mode = 1;        // 2 slots (int64) per sample
    else                     lab_mode = (rem > 0) ? 0 : 2;

    float4* w4 = (float4*)d_out;
    char* lab_out = (char*)d_out + n_w * sizeof(float);

    const long long n_threads = B * 25;           // 4 samples per thread
    const int block = 256;
    const long long grid = (n_threads + block - 1) / block;

    sampling_kernel<<<(unsigned)grid, block>>>(zm, lv, labels, eps4, w4,
                                               lab_out, lab_mode, n_threads);
}